// round 14
// baseline (speedup 1.0000x reference)
#include <cuda_runtime.h>
#include <math.h>

// BucketingBBoxCoder decode, GB300 sm_103a. Round 14: ILP=2 experiment.
// Stable baseline = ncu 42.5 +/- 0.7us over 6 builds (DRAM ~78%, LTS-capped).
// Untried axis: per-thread ILP. Each thread handles TWO proposals (p0 and
// p0+256, both coalesced) with ALL loads front-batched (no loop/branch between
// streams, unlike R7's fenced persistent loop). Doubles per-thread MLP to ~16;
// halves per-byte issue overhead. regs ~88 @ (256,2).

#define TOTAL (8 * 131072)       // 1,048,576 proposals
#define SCALE_F 3.0f
#define INV_NB (1.0f / 14.0f)
#define W_CLAMP 1332.0f
#define H_CLAMP 799.0f

__device__ __forceinline__ void decode_one(
    const float4 pr, const float* __restrict__ c,
    const float* __restrict__ offp,
    float4* __restrict__ out_bbox, float* __restrict__ out_conf, int p)
{
    const float cx = (pr.x + pr.z) * 0.5f;
    const float cy = (pr.y + pr.w) * 0.5f;
    const float pw = (pr.z - pr.x) * SCALE_F;
    const float ph = (pr.w - pr.y) * SCALE_F;
    const float px1 = cx - 0.5f * pw;
    const float px2 = cx + 0.5f * pw;
    const float py1 = cy - 0.5f * ph;
    const float py2 = cy + 0.5f * ph;
    const float bw = pw * INV_NB;
    const float bh = ph * INV_NB;

    const float edge_base[4] = { px1, px2, py1, py2 };
    const float edge_sign[4] = { 1.0f, -1.0f, 1.0f, -1.0f };
    const float edge_bsz [4] = { bw, bw, bh, bh };
    const float edge_hi  [4] = { W_CLAMP, W_CLAMP, H_CLAMP, H_CLAMP };

    int   i1v[4];
    float conf_sum = 0.0f;

#pragma unroll
    for (int e = 0; e < 4; e++) {
        float m1 = c[e*7 + 0]; int i1 = 0;
        float m2 = -INFINITY;  int i2 = 0;
#pragma unroll
        for (int s = 1; s < 7; s++) {
            const float v = c[e*7 + s];
            if (v > m1)      { m2 = m1; i2 = i1; m1 = v; i1 = s; }
            else if (v > m2) { m2 = v; i2 = s; }
        }

        float sum = 0.0f;
        float e2  = 0.0f;
#pragma unroll
        for (int s = 0; s < 7; s++) {
            const float ev = __expf(c[e*7 + s] - m1);
            sum += ev;
            e2 = (s == i2) ? ev : e2;
        }
        const float t1 = 1.0f / sum;
        const float t2 = e2 * t1;

        conf_sum += t1 + t2 * (fabsf((float)(i1 - i2)) - 1.0f);
        i1v[e] = i1;
    }

    const float o0 = __ldcs(offp +  0 + i1v[0]);
    const float o1 = __ldcs(offp +  7 + i1v[1]);
    const float o2 = __ldcs(offp + 14 + i1v[2]);
    const float o3 = __ldcs(offp + 21 + i1v[3]);
    const float ov[4] = { o0, o1, o2, o3 };

    float coord[4];
#pragma unroll
    for (int e = 0; e < 4; e++) {
        float cval = edge_base[e]
                   + edge_sign[e] * (0.5f + (float)i1v[e]) * edge_bsz[e]
                   - ov[e] * edge_bsz[e];
        coord[e] = fminf(fmaxf(cval, 0.0f), edge_hi[e]);
    }

    float4 bb;
    bb.x = coord[0];
    bb.y = coord[2];
    bb.z = coord[1];
    bb.w = coord[3];
    __stcs(&out_bbox[p], bb);
    __stcs(&out_conf[p], conf_sum * 0.25f);
}

__global__ __launch_bounds__(256, 2)
void bucketing_bbox_kernel(const float4* __restrict__ proposals,   // [TOTAL] float4
                           const float4* __restrict__ cls4,        // [TOTAL*7] float4
                           const float*  __restrict__ off,         // [TOTAL*28] float
                           float4* __restrict__ out_bbox,          // [TOTAL] float4
                           float* __restrict__ out_conf)           // [TOTAL]
{
    // each block covers 512 consecutive proposals: thread t -> p0 = base+t,
    // p1 = base+t+256. Both streams fully coalesced.
    const int p0 = blockIdx.x * 512 + threadIdx.x;
    const int p1 = p0 + 256;

    // ---- front-batched loads for BOTH streams (MLP ~16) ----
    const float4 pr0 = __ldcs(&proposals[p0]);
    const float4 pr1 = __ldcs(&proposals[p1]);

    const size_t b0 = (size_t)p0 * 7;
    const size_t b1 = (size_t)p1 * 7;
    float c0[28], c1[28];
#pragma unroll
    for (int k = 0; k < 7; k++) {
        float4 v = __ldcs(&cls4[b0 + k]);
        c0[4*k+0] = v.x; c0[4*k+1] = v.y; c0[4*k+2] = v.z; c0[4*k+3] = v.w;
    }
#pragma unroll
    for (int k = 0; k < 7; k++) {
        float4 v = __ldcs(&cls4[b1 + k]);
        c1[4*k+0] = v.x; c1[4*k+1] = v.y; c1[4*k+2] = v.z; c1[4*k+3] = v.w;
    }

    decode_one(pr0, c0, off + (size_t)p0 * 28, out_bbox, out_conf, p0);
    decode_one(pr1, c1, off + (size_t)p1 * 28, out_bbox, out_conf, p1);
}

extern "C" void kernel_launch(void* const* d_in, const int* in_sizes, int n_in,
                              void* d_out, int out_size)
{
    const float4* proposals = (const float4*)d_in[0];
    const float4* cls4      = (const float4*)d_in[1];
    const float*  off       = (const float*)d_in[2];

    float4* out_bbox = (float4*)d_out;
    float*  out_conf = (float*)d_out + (size_t)TOTAL * 4;

    const int blocks = TOTAL / 512;   // 2048
    bucketing_bbox_kernel<<<blocks, 256>>>(proposals, cls4, off,
                                           out_bbox, out_conf);
}